// round 2
// baseline (speedup 1.0000x reference)
#include <cuda_runtime.h>

#define B_ 8
#define C_ 192
#define N_ 16384
#define NH_ 6
#define HD_ 32

// Scratch (device globals: allocation-free per harness rules)
__device__ float g_q[B_*C_*N_];
__device__ float g_k[B_*C_*N_];
__device__ float g_v[B_*C_*N_];
__device__ float g_ssq[B_*C_];
__device__ float g_ssk[B_*C_];
__device__ float g_G[B_*NH_*HD_*HD_];
__device__ float g_M[B_*C_*C_];

__device__ __forceinline__ unsigned long long pack2(float lo, float hi) {
    unsigned long long r;
    asm("mov.b64 %0, {%1, %2};" : "=l"(r) : "f"(lo), "f"(hi));
    return r;
}
__device__ __forceinline__ void fma2(unsigned long long& d, unsigned long long a,
                                     unsigned long long b, unsigned long long c) {
    asm("fma.rn.f32x2 %0, %1, %2, %3;" : "=l"(d) : "l"(a), "l"(b), "l"(c));
}
__device__ __forceinline__ float2 unpack2(unsigned long long v) {
    float2 f;
    f.x = __uint_as_float((unsigned int)(v & 0xffffffffull));
    f.y = __uint_as_float((unsigned int)(v >> 32));
    return f;
}

// ---------------------------------------------------------------------------
// K1: depthwise 3x3 conv (groups = C). Block = (b, cin). Input channel cin
// feeds output channels 3*cin..3*cin+2 (all landing in the same one of q/k/v).
// For q/k channels also computes the full per-channel sum-of-squares (block
// covers the whole plane -> direct store, no atomics).
// ---------------------------------------------------------------------------
__global__ __launch_bounds__(256) void conv_qkv_k(const float* __restrict__ x,
                                                  const float* __restrict__ w,
                                                  const float* __restrict__ bias) {
    const int RS = 132;
    extern __shared__ float tile[];
    int cin = blockIdx.x, b = blockIdx.y;
    const float* xp = x + ((size_t)b * C_ + cin) * N_;
    for (int i = threadIdx.x; i < 130 * 130; i += 256) {
        int r = i / 130, c = i - r * 130;
        int yy = r - 1, xx = c - 1;
        float v = 0.f;
        if ((unsigned)yy < 128u && (unsigned)xx < 128u) v = xp[yy * 128 + xx];
        tile[r * RS + c] = v;
    }
    __syncthreads();

    int o0 = cin * 3;
    float w9[3][9], bs[3];
    float* dst[3];
#pragma unroll
    for (int j = 0; j < 3; j++) {
        int o = o0 + j;
        bs[j] = bias[o];
#pragma unroll
        for (int t = 0; t < 9; t++) w9[j][t] = w[o * 9 + t];
        float* base; int oc;
        if (o < C_)          { base = g_q; oc = o; }
        else if (o < 2 * C_) { base = g_k; oc = o - C_; }
        else                 { base = g_v; oc = o - 2 * C_; }
        dst[j] = base + ((size_t)b * C_ + oc) * N_;
    }
    bool needss = (o0 < 2 * C_);
    float ss0 = 0.f, ss1 = 0.f, ss2 = 0.f;

    for (int p = threadIdx.x; p < N_; p += 256) {
        int r = p >> 7, c = p & 127;
        float in9[9];
#pragma unroll
        for (int dy = 0; dy < 3; dy++)
#pragma unroll
            for (int dx = 0; dx < 3; dx++)
                in9[dy * 3 + dx] = tile[(r + dy) * RS + (c + dx)];
#pragma unroll
        for (int j = 0; j < 3; j++) {
            float acc = bs[j];
#pragma unroll
            for (int t = 0; t < 9; t++) acc = fmaf(in9[t], w9[j][t], acc);
            dst[j][p] = acc;
            if (needss) {
                if (j == 0)      ss0 = fmaf(acc, acc, ss0);
                else if (j == 1) ss1 = fmaf(acc, acc, ss1);
                else             ss2 = fmaf(acc, acc, ss2);
            }
        }
    }
    if (needss) {
        __shared__ float red[3][8];
        float s3[3] = {ss0, ss1, ss2};
#pragma unroll
        for (int j = 0; j < 3; j++) {
            float v = s3[j];
#pragma unroll
            for (int off = 16; off > 0; off >>= 1) v += __shfl_xor_sync(0xffffffffu, v, off);
            if ((threadIdx.x & 31) == 0) red[j][threadIdx.x >> 5] = v;
        }
        __syncthreads();
        if (threadIdx.x < 3) {
            float t = 0.f;
#pragma unroll
            for (int wd = 0; wd < 8; wd++) t += red[threadIdx.x][wd];
            int o = o0 + threadIdx.x;
            if (o < C_) g_ssq[b * C_ + o] = t;
            else        g_ssk[b * C_ + (o - C_)] = t;
        }
    }
}

// ---------------------------------------------------------------------------
// zero the gram accumulator
// ---------------------------------------------------------------------------
__global__ void zero_g_k() { g_G[blockIdx.x * 1024 + threadIdx.x] = 0.f; }

// ---------------------------------------------------------------------------
// K2: raw gram G[b,h] = q_h @ k_h^T over N, chunked (8 chunks of 2048) with
// fp32 atomics. Normalization is applied later (it factors out of the sum).
// ---------------------------------------------------------------------------
__global__ __launch_bounds__(256) void gram_k() {
    int chunk = blockIdx.x, h = blockIdx.y, b = blockIdx.z;
    const float* qb = g_q + ((size_t)b * C_ + h * HD_) * N_;
    const float* kb = g_k + ((size_t)b * C_ + h * HD_) * N_;
    __shared__ float qs[HD_][65], ks[HD_][65];
    int tid = threadIdx.x;
    int tx = tid & 15, ty = tid >> 4;
    float a00 = 0.f, a01 = 0.f, a10 = 0.f, a11 = 0.f;
    int n0 = chunk * 2048;
    for (int nb = 0; nb < 2048; nb += 64) {
        for (int i = tid; i < 32 * 64; i += 256) {
            int cc = i >> 6, t = i & 63;
            qs[cc][t] = qb[(size_t)cc * N_ + n0 + nb + t];
            ks[cc][t] = kb[(size_t)cc * N_ + n0 + nb + t];
        }
        __syncthreads();
#pragma unroll 8
        for (int t = 0; t < 64; t++) {
            float q0 = qs[2 * ty][t], q1 = qs[2 * ty + 1][t];
            float k0 = ks[2 * tx][t], k1 = ks[2 * tx + 1][t];
            a00 = fmaf(q0, k0, a00); a01 = fmaf(q0, k1, a01);
            a10 = fmaf(q1, k0, a10); a11 = fmaf(q1, k1, a11);
        }
        __syncthreads();
    }
    float* Gp = g_G + ((b * NH_ + h) << 10);
    atomicAdd(&Gp[(2 * ty) * 32 + 2 * tx],         a00);
    atomicAdd(&Gp[(2 * ty) * 32 + 2 * tx + 1],     a01);
    atomicAdd(&Gp[(2 * ty + 1) * 32 + 2 * tx],     a10);
    atomicAdd(&Gp[(2 * ty + 1) * 32 + 2 * tx + 1], a11);
}

// ---------------------------------------------------------------------------
// K3: scale gram by temperature/(||q||·||k||), softmax rows, then compose the
// full per-batch output matrix M[b] = w_out @ blockdiag(attn heads).
// ---------------------------------------------------------------------------
__global__ __launch_bounds__(256) void attn_compose_k(const float* __restrict__ temp,
                                                      const float* __restrict__ w_out) {
    int b = blockIdx.x;
    __shared__ float A[NH_][HD_][HD_];
    int tid = threadIdx.x;
    if (tid < 192) {
        int h = tid >> 5, cl = tid & 31;
        float nq = fmaxf(sqrtf(g_ssq[b * C_ + h * HD_ + cl]), 1e-12f);
        float tp = temp[h];
        const float* Gr = g_G + ((b * NH_ + h) << 10) + cl * HD_;
        float row[32], mx = -3.4e38f;
#pragma unroll
        for (int d = 0; d < 32; d++) {
            float nk = fmaxf(sqrtf(g_ssk[b * C_ + h * HD_ + d]), 1e-12f);
            float v = Gr[d] * tp / (nq * nk);
            row[d] = v;
            mx = fmaxf(mx, v);
        }
        float s = 0.f;
#pragma unroll
        for (int d = 0; d < 32; d++) { row[d] = expf(row[d] - mx); s += row[d]; }
        float inv = 1.f / s;
#pragma unroll
        for (int d = 0; d < 32; d++) A[h][cl][d] = row[d] * inv;
    }
    __syncthreads();
    float* Mb = g_M + (size_t)b * C_ * C_;
    for (int i = tid; i < C_ * C_; i += 256) {
        int o = i / 192, g = i - o * 192;
        int h = g >> 5, d = g & 31;
        const float* wr = w_out + o * C_ + h * HD_;
        float acc = 0.f;
#pragma unroll
        for (int cl = 0; cl < 32; cl++) acc = fmaf(wr[cl], A[h][cl][d], acc);
        Mb[i] = acc;
    }
}

// ---------------------------------------------------------------------------
// K4: out[b] = M[b](192x192) @ v[b](192xN) + b_out, via packed f32x2 FMA.
// Block tile: all 192 rows x 64 cols. SMEM: M transposed (k-major, pad 193)
// + v tile (pad 72). Thread tile: 6 rows x 8 cols (4 f32x2 pairs).
// ---------------------------------------------------------------------------
__global__ __launch_bounds__(256) void gemm_out_k(const float* __restrict__ b_out,
                                                  float* __restrict__ out) {
    extern __shared__ float sm[];
    float* Ms = sm;               // [k][o], stride 193
    float* Vs = sm + 192 * 193;   // [k][c], stride 72
    int b = blockIdx.y;
    int n0 = blockIdx.x * 64;
    int tid = threadIdx.x;

    const float* Mg = g_M + (size_t)b * C_ * C_;
    for (int i = tid; i < C_ * C_; i += 256) {
        int o = i / 192, kk = i - o * 192;
        Ms[kk * 193 + o] = Mg[i];
    }
    const float* vb = g_v + (size_t)b * C_ * N_ + n0;
    for (int i = tid; i < 192 * 64; i += 256) {
        int kk = i >> 6, c = i & 63;
        Vs[kk * 72 + c] = vb[(size_t)kk * N_ + c];
    }
    __syncthreads();

    int tx = tid & 7, ty = tid >> 3;
    int r0 = ty * 6;
    unsigned long long acc[6][4];
#pragma unroll
    for (int j = 0; j < 6; j++)
#pragma unroll
        for (int p = 0; p < 4; p++) acc[j][p] = 0ull;

#pragma unroll 2
    for (int kk = 0; kk < 192; kk++) {
        const float* vr = Vs + kk * 72 + tx * 8;
        ulonglong2 va  = *(const ulonglong2*)vr;
        ulonglong2 vb2 = *(const ulonglong2*)(vr + 4);
        unsigned long long vv0 = va.x, vv1 = va.y, vv2 = vb2.x, vv3 = vb2.y;
        const float* mr = Ms + kk * 193 + r0;
#pragma unroll
        for (int j = 0; j < 6; j++) {
            float m = mr[j];
            unsigned long long mm = pack2(m, m);
            fma2(acc[j][0], mm, vv0, acc[j][0]);
            fma2(acc[j][1], mm, vv1, acc[j][1]);
            fma2(acc[j][2], mm, vv2, acc[j][2]);
            fma2(acc[j][3], mm, vv3, acc[j][3]);
        }
    }

#pragma unroll
    for (int j = 0; j < 6; j++) {
        int r = r0 + j;
        float bb = b_out[r];
        float2 f0 = unpack2(acc[j][0]), f1 = unpack2(acc[j][1]);
        float2 f2 = unpack2(acc[j][2]), f3 = unpack2(acc[j][3]);
        float4 o0 = make_float4(f0.x + bb, f0.y + bb, f1.x + bb, f1.y + bb);
        float4 o1 = make_float4(f2.x + bb, f2.y + bb, f3.x + bb, f3.y + bb);
        float4* op = (float4*)(out + ((size_t)b * C_ + r) * N_ + n0 + tx * 8);
        op[0] = o0;
        op[1] = o1;
    }
}

// ---------------------------------------------------------------------------
extern "C" void kernel_launch(void* const* d_in, const int* in_sizes, int n_in,
                              void* d_out, int out_size) {
    const float* x     = (const float*)d_in[0];
    const float* w_qkv = (const float*)d_in[1];
    const float* b_qkv = (const float*)d_in[2];
    const float* temp  = (const float*)d_in[3];
    const float* w_out = (const float*)d_in[4];
    const float* b_out = (const float*)d_in[5];
    float* out = (float*)d_out;

    (void)in_sizes; (void)n_in; (void)out_size;

    cudaFuncSetAttribute(conv_qkv_k, cudaFuncAttributeMaxDynamicSharedMemorySize,
                         130 * 132 * 4);
    cudaFuncSetAttribute(gemm_out_k, cudaFuncAttributeMaxDynamicSharedMemorySize,
                         (192 * 193 + 192 * 72) * 4);

    conv_qkv_k<<<dim3(C_, B_), 256, 130 * 132 * 4>>>(x, w_qkv, b_qkv);
    zero_g_k<<<48, 1024>>>();
    gram_k<<<dim3(8, NH_, B_), 256>>>();
    attn_compose_k<<<B_, 256>>>(temp, w_out);
    gemm_out_k<<<dim3(N_ / 64, B_), 256, (192 * 193 + 192 * 72) * 4>>>(b_out, out);
}

// round 3
// speedup vs baseline: 1.0038x; 1.0038x over previous
#include <cuda_runtime.h>

#define B_ 8
#define C_ 192
#define N_ 16384
#define NH_ 6
#define HD_ 32

// Scratch (device globals: allocation-free per harness rules)
__device__ float g_q[B_*C_*N_];
__device__ float g_k[B_*C_*N_];
__device__ float g_v[B_*C_*N_];
__device__ float g_ssq[B_*C_];
__device__ float g_ssk[B_*C_];
__device__ float g_G[B_*NH_*HD_*HD_];
__device__ float g_M[B_*C_*C_];

__device__ __forceinline__ unsigned long long pack2(float lo, float hi) {
    unsigned long long r;
    asm("mov.b64 %0, {%1, %2};" : "=l"(r) : "f"(lo), "f"(hi));
    return r;
}
__device__ __forceinline__ void fma2(unsigned long long& d, unsigned long long a,
                                     unsigned long long b, unsigned long long c) {
    asm("fma.rn.f32x2 %0, %1, %2, %3;" : "=l"(d) : "l"(a), "l"(b), "l"(c));
}
__device__ __forceinline__ float2 unpack2(unsigned long long v) {
    float2 f;
    f.x = __uint_as_float((unsigned int)(v & 0xffffffffull));
    f.y = __uint_as_float((unsigned int)(v >> 32));
    return f;
}

// ---------------------------------------------------------------------------
// K1: depthwise 3x3 conv (groups = C). Block = (b, cin). Input channel cin
// feeds output channels 3*cin..3*cin+2 (all landing in the same one of q/k/v).
// For q/k channels also computes the full per-channel sum-of-squares (block
// covers the whole plane -> direct store, no atomics).
// ---------------------------------------------------------------------------
__global__ __launch_bounds__(256) void conv_qkv_k(const float* __restrict__ x,
                                                  const float* __restrict__ w,
                                                  const float* __restrict__ bias) {
    const int RS = 132;
    extern __shared__ float tile[];
    int cin = blockIdx.x, b = blockIdx.y;
    const float* xp = x + ((size_t)b * C_ + cin) * N_;
    for (int i = threadIdx.x; i < 130 * 130; i += 256) {
        int r = i / 130, c = i - r * 130;
        int yy = r - 1, xx = c - 1;
        float v = 0.f;
        if ((unsigned)yy < 128u && (unsigned)xx < 128u) v = xp[yy * 128 + xx];
        tile[r * RS + c] = v;
    }
    __syncthreads();

    int o0 = cin * 3;
    float w9[3][9], bs[3];
    float* dst[3];
#pragma unroll
    for (int j = 0; j < 3; j++) {
        int o = o0 + j;
        bs[j] = bias[o];
#pragma unroll
        for (int t = 0; t < 9; t++) w9[j][t] = w[o * 9 + t];
        float* base; int oc;
        if (o < C_)          { base = g_q; oc = o; }
        else if (o < 2 * C_) { base = g_k; oc = o - C_; }
        else                 { base = g_v; oc = o - 2 * C_; }
        dst[j] = base + ((size_t)b * C_ + oc) * N_;
    }
    bool needss = (o0 < 2 * C_);
    float ss0 = 0.f, ss1 = 0.f, ss2 = 0.f;

    for (int p = threadIdx.x; p < N_; p += 256) {
        int r = p >> 7, c = p & 127;
        float in9[9];
#pragma unroll
        for (int dy = 0; dy < 3; dy++)
#pragma unroll
            for (int dx = 0; dx < 3; dx++)
                in9[dy * 3 + dx] = tile[(r + dy) * RS + (c + dx)];
#pragma unroll
        for (int j = 0; j < 3; j++) {
            float acc = bs[j];
#pragma unroll
            for (int t = 0; t < 9; t++) acc = fmaf(in9[t], w9[j][t], acc);
            dst[j][p] = acc;
            if (needss) {
                if (j == 0)      ss0 = fmaf(acc, acc, ss0);
                else if (j == 1) ss1 = fmaf(acc, acc, ss1);
                else             ss2 = fmaf(acc, acc, ss2);
            }
        }
    }
    if (needss) {
        __shared__ float red[3][8];
        float s3[3] = {ss0, ss1, ss2};
#pragma unroll
        for (int j = 0; j < 3; j++) {
            float v = s3[j];
#pragma unroll
            for (int off = 16; off > 0; off >>= 1) v += __shfl_xor_sync(0xffffffffu, v, off);
            if ((threadIdx.x & 31) == 0) red[j][threadIdx.x >> 5] = v;
        }
        __syncthreads();
        if (threadIdx.x < 3) {
            float t = 0.f;
#pragma unroll
            for (int wd = 0; wd < 8; wd++) t += red[threadIdx.x][wd];
            int o = o0 + threadIdx.x;
            if (o < C_) g_ssq[b * C_ + o] = t;
            else        g_ssk[b * C_ + (o - C_)] = t;
        }
    }
}

// ---------------------------------------------------------------------------
// zero the gram accumulator
// ---------------------------------------------------------------------------
__global__ void zero_g_k() { g_G[blockIdx.x * 1024 + threadIdx.x] = 0.f; }

// ---------------------------------------------------------------------------
// K2: raw gram G[b,h] = q_h @ k_h^T over N, chunked (8 chunks of 2048) with
// fp32 atomics. Normalization is applied later (it factors out of the sum).
// ---------------------------------------------------------------------------
__global__ __launch_bounds__(256) void gram_k() {
    int chunk = blockIdx.x, h = blockIdx.y, b = blockIdx.z;
    const float* qb = g_q + ((size_t)b * C_ + h * HD_) * N_;
    const float* kb = g_k + ((size_t)b * C_ + h * HD_) * N_;
    __shared__ float qs[HD_][65], ks[HD_][65];
    int tid = threadIdx.x;
    int tx = tid & 15, ty = tid >> 4;
    float a00 = 0.f, a01 = 0.f, a10 = 0.f, a11 = 0.f;
    int n0 = chunk * 2048;
    for (int nb = 0; nb < 2048; nb += 64) {
        for (int i = tid; i < 32 * 64; i += 256) {
            int cc = i >> 6, t = i & 63;
            qs[cc][t] = qb[(size_t)cc * N_ + n0 + nb + t];
            ks[cc][t] = kb[(size_t)cc * N_ + n0 + nb + t];
        }
        __syncthreads();
#pragma unroll 8
        for (int t = 0; t < 64; t++) {
            float q0 = qs[2 * ty][t], q1 = qs[2 * ty + 1][t];
            float k0 = ks[2 * tx][t], k1 = ks[2 * tx + 1][t];
            a00 = fmaf(q0, k0, a00); a01 = fmaf(q0, k1, a01);
            a10 = fmaf(q1, k0, a10); a11 = fmaf(q1, k1, a11);
        }
        __syncthreads();
    }
    float* Gp = g_G + ((b * NH_ + h) << 10);
    atomicAdd(&Gp[(2 * ty) * 32 + 2 * tx],         a00);
    atomicAdd(&Gp[(2 * ty) * 32 + 2 * tx + 1],     a01);
    atomicAdd(&Gp[(2 * ty + 1) * 32 + 2 * tx],     a10);
    atomicAdd(&Gp[(2 * ty + 1) * 32 + 2 * tx + 1], a11);
}

// ---------------------------------------------------------------------------
// K3: scale gram by temperature/(||q||·||k||), softmax rows, then compose the
// full per-batch output matrix M[b] = w_out @ blockdiag(attn heads).
// ---------------------------------------------------------------------------
__global__ __launch_bounds__(256) void attn_compose_k(const float* __restrict__ temp,
                                                      const float* __restrict__ w_out) {
    int b = blockIdx.x;
    __shared__ float A[NH_][HD_][HD_];
    int tid = threadIdx.x;
    if (tid < 192) {
        int h = tid >> 5, cl = tid & 31;
        float nq = fmaxf(sqrtf(g_ssq[b * C_ + h * HD_ + cl]), 1e-12f);
        float tp = temp[h];
        const float* Gr = g_G + ((b * NH_ + h) << 10) + cl * HD_;
        float row[32], mx = -3.4e38f;
#pragma unroll
        for (int d = 0; d < 32; d++) {
            float nk = fmaxf(sqrtf(g_ssk[b * C_ + h * HD_ + d]), 1e-12f);
            float v = Gr[d] * tp / (nq * nk);
            row[d] = v;
            mx = fmaxf(mx, v);
        }
        float s = 0.f;
#pragma unroll
        for (int d = 0; d < 32; d++) { row[d] = expf(row[d] - mx); s += row[d]; }
        float inv = 1.f / s;
#pragma unroll
        for (int d = 0; d < 32; d++) A[h][cl][d] = row[d] * inv;
    }
    __syncthreads();
    float* Mb = g_M + (size_t)b * C_ * C_;
    for (int i = tid; i < C_ * C_; i += 256) {
        int o = i / 192, g = i - o * 192;
        int h = g >> 5, d = g & 31;
        const float* wr = w_out + o * C_ + h * HD_;
        float acc = 0.f;
#pragma unroll
        for (int cl = 0; cl < 32; cl++) acc = fmaf(wr[cl], A[h][cl][d], acc);
        Mb[i] = acc;
    }
}

// ---------------------------------------------------------------------------
// K4: out[b] = M[b](192x192) @ v[b](192xN) + b_out, via packed f32x2 FMA.
// Block tile: all 192 rows x 64 cols. SMEM: M transposed (k-major, pad 193)
// + v tile (pad 72). Thread tile: 6 rows x 8 cols (4 f32x2 pairs).
// ---------------------------------------------------------------------------
__global__ __launch_bounds__(256) void gemm_out_k(const float* __restrict__ b_out,
                                                  float* __restrict__ out) {
    extern __shared__ float sm[];
    float* Ms = sm;               // [k][o], stride 193
    float* Vs = sm + 192 * 193;   // [k][c], stride 72
    int b = blockIdx.y;
    int n0 = blockIdx.x * 64;
    int tid = threadIdx.x;

    const float* Mg = g_M + (size_t)b * C_ * C_;
    for (int i = tid; i < C_ * C_; i += 256) {
        int o = i / 192, kk = i - o * 192;
        Ms[kk * 193 + o] = Mg[i];
    }
    const float* vb = g_v + (size_t)b * C_ * N_ + n0;
    for (int i = tid; i < 192 * 64; i += 256) {
        int kk = i >> 6, c = i & 63;
        Vs[kk * 72 + c] = vb[(size_t)kk * N_ + c];
    }
    __syncthreads();

    int tx = tid & 7, ty = tid >> 3;
    int r0 = ty * 6;
    unsigned long long acc[6][4];
#pragma unroll
    for (int j = 0; j < 6; j++)
#pragma unroll
        for (int p = 0; p < 4; p++) acc[j][p] = 0ull;

#pragma unroll 2
    for (int kk = 0; kk < 192; kk++) {
        const float* vr = Vs + kk * 72 + tx * 8;
        ulonglong2 va  = *(const ulonglong2*)vr;
        ulonglong2 vb2 = *(const ulonglong2*)(vr + 4);
        unsigned long long vv0 = va.x, vv1 = va.y, vv2 = vb2.x, vv3 = vb2.y;
        const float* mr = Ms + kk * 193 + r0;
#pragma unroll
        for (int j = 0; j < 6; j++) {
            float m = mr[j];
            unsigned long long mm = pack2(m, m);
            fma2(acc[j][0], mm, vv0, acc[j][0]);
            fma2(acc[j][1], mm, vv1, acc[j][1]);
            fma2(acc[j][2], mm, vv2, acc[j][2]);
            fma2(acc[j][3], mm, vv3, acc[j][3]);
        }
    }

#pragma unroll
    for (int j = 0; j < 6; j++) {
        int r = r0 + j;
        float bb = b_out[r];
        float2 f0 = unpack2(acc[j][0]), f1 = unpack2(acc[j][1]);
        float2 f2 = unpack2(acc[j][2]), f3 = unpack2(acc[j][3]);
        float4 o0 = make_float4(f0.x + bb, f0.y + bb, f1.x + bb, f1.y + bb);
        float4 o1 = make_float4(f2.x + bb, f2.y + bb, f3.x + bb, f3.y + bb);
        float4* op = (float4*)(out + ((size_t)b * C_ + r) * N_ + n0 + tx * 8);
        op[0] = o0;
        op[1] = o1;
    }
}

// ---------------------------------------------------------------------------
extern "C" void kernel_launch(void* const* d_in, const int* in_sizes, int n_in,
                              void* d_out, int out_size) {
    const float* x     = (const float*)d_in[0];
    const float* w_qkv = (const float*)d_in[1];
    const float* b_qkv = (const float*)d_in[2];
    const float* temp  = (const float*)d_in[3];
    const float* w_out = (const float*)d_in[4];
    const float* b_out = (const float*)d_in[5];
    float* out = (float*)d_out;

    (void)in_sizes; (void)n_in; (void)out_size;

    cudaFuncSetAttribute(conv_qkv_k, cudaFuncAttributeMaxDynamicSharedMemorySize,
                         130 * 132 * 4);
    cudaFuncSetAttribute(gemm_out_k, cudaFuncAttributeMaxDynamicSharedMemorySize,
                         (192 * 193 + 192 * 72) * 4);

    conv_qkv_k<<<dim3(C_, B_), 256, 130 * 132 * 4>>>(x, w_qkv, b_qkv);
    zero_g_k<<<48, 1024>>>();
    gram_k<<<dim3(8, NH_, B_), 256>>>();
    attn_compose_k<<<B_, 256>>>(temp, w_out);
    gemm_out_k<<<dim3(N_ / 64, B_), 256, (192 * 193 + 192 * 72) * 4>>>(b_out, out);
}

// round 4
// speedup vs baseline: 1.5166x; 1.5109x over previous
#include <cuda_runtime.h>

#define B_ 8
#define C_ 192
#define N_ 16384
#define NH_ 6
#define HD_ 32

// Scratch (device globals: allocation-free per harness rules)
__device__ float g_q[B_*C_*N_];
__device__ float g_k[B_*C_*N_];
__device__ float g_v[B_*C_*N_];
__device__ float g_ssq[B_*C_];
__device__ float g_ssk[B_*C_];
__device__ float g_G[B_*NH_*HD_*HD_];
__device__ float g_M[B_*C_*C_];

__device__ __forceinline__ unsigned long long pack2(float lo, float hi) {
    unsigned long long r;
    asm("mov.b64 %0, {%1, %2};" : "=l"(r) : "f"(lo), "f"(hi));
    return r;
}
__device__ __forceinline__ void fma2(unsigned long long& d, unsigned long long a,
                                     unsigned long long b, unsigned long long c) {
    asm("fma.rn.f32x2 %0, %1, %2, %3;" : "=l"(d) : "l"(a), "l"(b), "l"(c));
}
__device__ __forceinline__ float2 unpack2(unsigned long long v) {
    float2 f;
    f.x = __uint_as_float((unsigned int)(v & 0xffffffffull));
    f.y = __uint_as_float((unsigned int)(v >> 32));
    return f;
}
__device__ __forceinline__ unsigned su32(const void* p) {
    unsigned r;
    asm("{ .reg .u64 t; cvta.to.shared.u64 t, %1; cvt.u32.u64 %0, t; }"
        : "=r"(r) : "l"(p));
    return r;
}
#define CP_ASYNC16(s, g) asm volatile("cp.async.ca.shared.global [%0], [%1], 16;" :: "r"(s), "l"(g))
#define CP_COMMIT()      asm volatile("cp.async.commit_group;")
#define CP_WAIT(n)       asm volatile("cp.async.wait_group %0;" :: "n"(n))

// ---------------------------------------------------------------------------
// K1: depthwise 3x3 conv (groups = C). Block = (b, cin). Input channel cin
// feeds output channels 3*cin..3*cin+2. For q/k channels also computes the
// full per-channel sum-of-squares (block covers the whole plane).
// ---------------------------------------------------------------------------
__global__ __launch_bounds__(256) void conv_qkv_k(const float* __restrict__ x,
                                                  const float* __restrict__ w,
                                                  const float* __restrict__ bias) {
    const int RS = 132;
    extern __shared__ float tile[];
    int cin = blockIdx.x, b = blockIdx.y;
    const float* xp = x + ((size_t)b * C_ + cin) * N_;
    for (int i = threadIdx.x; i < 130 * 130; i += 256) {
        int r = i / 130, c = i - r * 130;
        int yy = r - 1, xx = c - 1;
        float v = 0.f;
        if ((unsigned)yy < 128u && (unsigned)xx < 128u) v = xp[yy * 128 + xx];
        tile[r * RS + c] = v;
    }
    __syncthreads();

    int o0 = cin * 3;
    float w9[3][9], bs[3];
    float* dst[3];
#pragma unroll
    for (int j = 0; j < 3; j++) {
        int o = o0 + j;
        bs[j] = bias[o];
#pragma unroll
        for (int t = 0; t < 9; t++) w9[j][t] = w[o * 9 + t];
        float* base; int oc;
        if (o < C_)          { base = g_q; oc = o; }
        else if (o < 2 * C_) { base = g_k; oc = o - C_; }
        else                 { base = g_v; oc = o - 2 * C_; }
        dst[j] = base + ((size_t)b * C_ + oc) * N_;
    }
    bool needss = (o0 < 2 * C_);
    float ss0 = 0.f, ss1 = 0.f, ss2 = 0.f;

    for (int p = threadIdx.x; p < N_; p += 256) {
        int r = p >> 7, c = p & 127;
        float in9[9];
#pragma unroll
        for (int dy = 0; dy < 3; dy++)
#pragma unroll
            for (int dx = 0; dx < 3; dx++)
                in9[dy * 3 + dx] = tile[(r + dy) * RS + (c + dx)];
#pragma unroll
        for (int j = 0; j < 3; j++) {
            float acc = bs[j];
#pragma unroll
            for (int t = 0; t < 9; t++) acc = fmaf(in9[t], w9[j][t], acc);
            dst[j][p] = acc;
            if (needss) {
                if (j == 0)      ss0 = fmaf(acc, acc, ss0);
                else if (j == 1) ss1 = fmaf(acc, acc, ss1);
                else             ss2 = fmaf(acc, acc, ss2);
            }
        }
    }
    if (needss) {
        __shared__ float red[3][8];
        float s3[3] = {ss0, ss1, ss2};
#pragma unroll
        for (int j = 0; j < 3; j++) {
            float v = s3[j];
#pragma unroll
            for (int off = 16; off > 0; off >>= 1) v += __shfl_xor_sync(0xffffffffu, v, off);
            if ((threadIdx.x & 31) == 0) red[j][threadIdx.x >> 5] = v;
        }
        __syncthreads();
        if (threadIdx.x < 3) {
            float t = 0.f;
#pragma unroll
            for (int wd = 0; wd < 8; wd++) t += red[threadIdx.x][wd];
            int o = o0 + threadIdx.x;
            if (o < C_) g_ssq[b * C_ + o] = t;
            else        g_ssk[b * C_ + (o - C_)] = t;
        }
    }
}

// ---------------------------------------------------------------------------
__global__ void zero_g_k() { g_G[blockIdx.x * 1024 + threadIdx.x] = 0.f; }

// ---------------------------------------------------------------------------
// K2: raw gram G[b,h] = q_h @ k_h^T over N, chunked with fp32 atomics.
// ---------------------------------------------------------------------------
__global__ __launch_bounds__(256) void gram_k() {
    int chunk = blockIdx.x, h = blockIdx.y, b = blockIdx.z;
    const float* qb = g_q + ((size_t)b * C_ + h * HD_) * N_;
    const float* kb = g_k + ((size_t)b * C_ + h * HD_) * N_;
    __shared__ float qs[HD_][65], ks[HD_][65];
    int tid = threadIdx.x;
    int tx = tid & 15, ty = tid >> 4;
    float a00 = 0.f, a01 = 0.f, a10 = 0.f, a11 = 0.f;
    int n0 = chunk * 2048;
    for (int nb = 0; nb < 2048; nb += 64) {
        for (int i = tid; i < 32 * 64; i += 256) {
            int cc = i >> 6, t = i & 63;
            qs[cc][t] = qb[(size_t)cc * N_ + n0 + nb + t];
            ks[cc][t] = kb[(size_t)cc * N_ + n0 + nb + t];
        }
        __syncthreads();
#pragma unroll 8
        for (int t = 0; t < 64; t++) {
            float q0 = qs[2 * ty][t], q1 = qs[2 * ty + 1][t];
            float k0 = ks[2 * tx][t], k1 = ks[2 * tx + 1][t];
            a00 = fmaf(q0, k0, a00); a01 = fmaf(q0, k1, a01);
            a10 = fmaf(q1, k0, a10); a11 = fmaf(q1, k1, a11);
        }
        __syncthreads();
    }
    float* Gp = g_G + ((b * NH_ + h) << 10);
    atomicAdd(&Gp[(2 * ty) * 32 + 2 * tx],         a00);
    atomicAdd(&Gp[(2 * ty) * 32 + 2 * tx + 1],     a01);
    atomicAdd(&Gp[(2 * ty + 1) * 32 + 2 * tx],     a10);
    atomicAdd(&Gp[(2 * ty + 1) * 32 + 2 * tx + 1], a11);
}

// ---------------------------------------------------------------------------
// K3a: per-(b,h) normalize+softmax, in place in g_G. One warp per (b,h).
// ---------------------------------------------------------------------------
__global__ __launch_bounds__(32) void softmax_k(const float* __restrict__ temp) {
    int h = blockIdx.x, b = blockIdx.y, cl = threadIdx.x;
    __shared__ float sinv[32];
    float nk = fmaxf(sqrtf(g_ssk[b * C_ + h * HD_ + cl]), 1e-12f);
    sinv[cl] = 1.f / nk;
    __syncwarp();
    float nq = fmaxf(sqrtf(g_ssq[b * C_ + h * HD_ + cl]), 1e-12f);
    float sc = temp[h] / nq;
    float* Gr = g_G + ((b * NH_ + h) << 10) + cl * HD_;
    float row[32], mx = -3.4e38f;
#pragma unroll
    for (int d = 0; d < 32; d++) {
        float v = Gr[d] * sc * sinv[d];
        row[d] = v;
        mx = fmaxf(mx, v);
    }
    float s = 0.f;
#pragma unroll
    for (int d = 0; d < 32; d++) { row[d] = expf(row[d] - mx); s += row[d]; }
    float inv = 1.f / s;
#pragma unroll
    for (int d = 0; d < 32; d++) Gr[d] = row[d] * inv;
}

// ---------------------------------------------------------------------------
// K3b: compose M[b] = w_out @ blockdiag(attn heads). grid (6 o-chunks, B).
// ---------------------------------------------------------------------------
__global__ __launch_bounds__(256) void compose_k(const float* __restrict__ w_out) {
    extern __shared__ float cs[];
    float* A   = cs;          // [6*32*32] softmaxed attn for this batch
    float* Wsh = cs + 6144;   // [32*192] w_out rows o0..o0+31
    int oc = blockIdx.x, b = blockIdx.y;
    int o0 = oc * 32;
    int tid = threadIdx.x;
    const float* Gb = g_G + ((size_t)b * NH_) * 1024;
    for (int i = tid; i < 6144; i += 256) A[i] = Gb[i];
    for (int i = tid; i < 32 * 192; i += 256) {
        int o = i / 192, c = i - o * 192;
        Wsh[i] = w_out[(o0 + o) * C_ + c];
    }
    __syncthreads();
    float* Mb = g_M + (size_t)b * C_ * C_ + (size_t)o0 * C_;
    for (int i = tid; i < 32 * 192; i += 256) {
        int o = i / 192, g = i - o * 192;
        int h = g >> 5, d = g & 31;
        const float* wr = Wsh + o * 192 + h * 32;
        const float* Ar = A + h * 1024 + d;
        float acc = 0.f;
#pragma unroll
        for (int cl = 0; cl < 32; cl++) acc = fmaf(wr[cl], Ar[cl * 32], acc);
        Mb[i] = acc;
    }
}

// ---------------------------------------------------------------------------
// K4: out[b] = M[b](192x192) @ v[b](192xN) + b_out via packed f32x2 FMA.
// 512 threads, block tile 192 rows x 128 cols, k double-buffered via cp.async.
// Thread tile: 6 rows x 8 cols (cols split as [tx*4, tx*4+4) and +64 so each
// LDS.128 phase is conflict-free).
// ---------------------------------------------------------------------------
#define KC 32
__global__ __launch_bounds__(512) void gemm_out_k(const float* __restrict__ b_out,
                                                  float* __restrict__ out) {
    extern __shared__ float sm[];
    float* Ms = sm;               // [192][193] k-major (Ms[k*193+o])
    float* Vs = sm + 192 * 193;   // [2][KC][132]
    int b = blockIdx.y;
    int n0 = blockIdx.x * 128;
    int tid = threadIdx.x;

    const float* Mg = g_M + (size_t)b * C_ * C_;
    const float* vb = g_v + (size_t)b * C_ * N_ + n0;

    // prefetch chunk 0 of v
    {
        int e = tid * 8;
        int kk = e >> 7, c = e & 127;
        const float* gp = vb + (size_t)kk * N_ + c;
        unsigned sp = su32(&Vs[kk * 132 + c]);
        CP_ASYNC16(sp, gp);
        CP_ASYNC16(sp + 16, gp + 4);
        CP_COMMIT();
    }
    // stage M (transposed to k-major)
    for (int i = tid; i < C_ * C_; i += 512) {
        int o = i / 192, kk = i - o * 192;
        Ms[kk * 193 + o] = Mg[i];
    }

    int tx = tid & 15, ty = tid >> 4;
    int r0 = ty * 6, c0 = tx * 4;

    unsigned long long acc[6][4];
#pragma unroll
    for (int j = 0; j < 6; j++)
#pragma unroll
        for (int p = 0; p < 4; p++) acc[j][p] = 0ull;

    for (int ch = 0; ch < 6; ch++) {
        if (ch < 5) {
            int e = tid * 8;
            int kk = e >> 7, c = e & 127;
            const float* gp = vb + (size_t)((ch + 1) * KC + kk) * N_ + c;
            unsigned sp = su32(&Vs[((ch + 1) & 1) * KC * 132 + kk * 132 + c]);
            CP_ASYNC16(sp, gp);
            CP_ASYNC16(sp + 16, gp + 4);
            CP_COMMIT();
            CP_WAIT(1);
        } else {
            CP_WAIT(0);
        }
        __syncthreads();
        const float* Vc = Vs + (ch & 1) * KC * 132;
        const float* Mc = Ms + ch * KC * 193;
#pragma unroll 4
        for (int kk = 0; kk < KC; kk++) {
            const float* vr = Vc + kk * 132;
            ulonglong2 va = *(const ulonglong2*)(vr + c0);
            ulonglong2 vb2 = *(const ulonglong2*)(vr + 64 + c0);
            unsigned long long vv0 = va.x, vv1 = va.y, vv2 = vb2.x, vv3 = vb2.y;
            const float* mr = Mc + kk * 193 + r0;
#pragma unroll
            for (int j = 0; j < 6; j++) {
                float m = mr[j];
                unsigned long long mm = pack2(m, m);
                fma2(acc[j][0], mm, vv0, acc[j][0]);
                fma2(acc[j][1], mm, vv1, acc[j][1]);
                fma2(acc[j][2], mm, vv2, acc[j][2]);
                fma2(acc[j][3], mm, vv3, acc[j][3]);
            }
        }
        __syncthreads();
    }

#pragma unroll
    for (int j = 0; j < 6; j++) {
        int r = r0 + j;
        float bb = b_out[r];
        float2 f0 = unpack2(acc[j][0]), f1 = unpack2(acc[j][1]);
        float2 f2 = unpack2(acc[j][2]), f3 = unpack2(acc[j][3]);
        float4 o0v = make_float4(f0.x + bb, f0.y + bb, f1.x + bb, f1.y + bb);
        float4 o1v = make_float4(f2.x + bb, f2.y + bb, f3.x + bb, f3.y + bb);
        float* op = out + ((size_t)b * C_ + r) * N_ + n0;
        *(float4*)(op + c0)      = o0v;
        *(float4*)(op + 64 + c0) = o1v;
    }
}

// ---------------------------------------------------------------------------
extern "C" void kernel_launch(void* const* d_in, const int* in_sizes, int n_in,
                              void* d_out, int out_size) {
    const float* x     = (const float*)d_in[0];
    const float* w_qkv = (const float*)d_in[1];
    const float* b_qkv = (const float*)d_in[2];
    const float* temp  = (const float*)d_in[3];
    const float* w_out = (const float*)d_in[4];
    const float* b_out = (const float*)d_in[5];
    float* out = (float*)d_out;

    (void)in_sizes; (void)n_in; (void)out_size;

    static int inited = 0;
    const int conv_smem = 130 * 132 * 4;
    const int gemm_smem = (192 * 193 + 2 * KC * 132) * 4;
    const int comp_smem = (6144 + 32 * 192) * 4;
    if (!inited) {
        cudaFuncSetAttribute(conv_qkv_k, cudaFuncAttributeMaxDynamicSharedMemorySize, conv_smem);
        cudaFuncSetAttribute(gemm_out_k, cudaFuncAttributeMaxDynamicSharedMemorySize, gemm_smem);
        cudaFuncSetAttribute(compose_k,  cudaFuncAttributeMaxDynamicSharedMemorySize, comp_smem);
        inited = 1;
    }

    conv_qkv_k<<<dim3(C_, B_), 256, conv_smem>>>(x, w_qkv, b_qkv);
    zero_g_k<<<48, 1024>>>();
    gram_k<<<dim3(8, NH_, B_), 256>>>();
    softmax_k<<<dim3(NH_, B_), 32>>>(temp);
    compose_k<<<dim3(6, B_), 256, comp_smem>>>(w_out);
    gemm_out_k<<<dim3(N_ / 128, B_), 512, gemm_smem>>>(b_out, out);
}

// round 5
// speedup vs baseline: 1.9746x; 1.3021x over previous
#include <cuda_runtime.h>
#include <cuda_bf16.h>

#define B_ 8
#define C_ 192
#define N_ 16384
#define NH_ 6
#define HD_ 32

// Scratch (device globals: allocation-free per harness rules)
__device__ __nv_bfloat16 g_q[B_*C_*N_];
__device__ __nv_bfloat16 g_k[B_*C_*N_];
__device__ float g_v[B_*C_*N_];
__device__ float g_ssq[B_*C_];
__device__ float g_ssk[B_*C_];
__device__ float g_G[B_*NH_*HD_*HD_];
__device__ float g_M[B_*C_*C_];

__device__ __forceinline__ unsigned long long pack2(float lo, float hi) {
    unsigned long long r;
    asm("mov.b64 %0, {%1, %2};" : "=l"(r) : "f"(lo), "f"(hi));
    return r;
}
__device__ __forceinline__ void fma2(unsigned long long& d, unsigned long long a,
                                     unsigned long long b, unsigned long long c) {
    asm("fma.rn.f32x2 %0, %1, %2, %3;" : "=l"(d) : "l"(a), "l"(b), "l"(c));
}
__device__ __forceinline__ float2 unpack2(unsigned long long v) {
    float2 f;
    f.x = __uint_as_float((unsigned int)(v & 0xffffffffull));
    f.y = __uint_as_float((unsigned int)(v >> 32));
    return f;
}
__device__ __forceinline__ unsigned su32(const void* p) {
    unsigned r;
    asm("{ .reg .u64 t; cvta.to.shared.u64 t, %1; cvt.u32.u64 %0, t; }"
        : "=r"(r) : "l"(p));
    return r;
}
#define CP_ASYNC16(s, g) asm volatile("cp.async.ca.shared.global [%0], [%1], 16;" :: "r"(s), "l"(g))
#define CP_COMMIT()      asm volatile("cp.async.commit_group;")
#define CP_WAIT(n)       asm volatile("cp.async.wait_group %0;" :: "n"(n))

// ---------------------------------------------------------------------------
// K-conv (q,k): cin 0..127 -> bf16 q/k planes + per-channel sum-of-squares
// (ssq computed on the ROUNDED bf16 values for consistency with the gram).
// ---------------------------------------------------------------------------
__global__ __launch_bounds__(256) void conv_qk_k(const float* __restrict__ x,
                                                 const float* __restrict__ w,
                                                 const float* __restrict__ bias) {
    const int RS = 132;
    extern __shared__ float tile[];
    int cin = blockIdx.x, b = blockIdx.y;
    const float* xp = x + ((size_t)b * C_ + cin) * N_;
    for (int i = threadIdx.x; i < 130 * 130; i += 256) {
        int r = i / 130, c = i - r * 130;
        int yy = r - 1, xx = c - 1;
        float v = 0.f;
        if ((unsigned)yy < 128u && (unsigned)xx < 128u) v = xp[yy * 128 + xx];
        tile[r * RS + c] = v;
    }
    __syncthreads();

    int o0 = cin * 3;
    float w9[3][9], bs[3];
    __nv_bfloat16* dst[3];
#pragma unroll
    for (int j = 0; j < 3; j++) {
        int o = o0 + j;
        bs[j] = bias[o];
#pragma unroll
        for (int t = 0; t < 9; t++) w9[j][t] = w[o * 9 + t];
        if (o < C_) dst[j] = g_q + ((size_t)b * C_ + o) * N_;
        else        dst[j] = g_k + ((size_t)b * C_ + (o - C_)) * N_;
    }
    float ss0 = 0.f, ss1 = 0.f, ss2 = 0.f;

    for (int p = threadIdx.x; p < N_; p += 256) {
        int r = p >> 7, c = p & 127;
        float in9[9];
#pragma unroll
        for (int dy = 0; dy < 3; dy++)
#pragma unroll
            for (int dx = 0; dx < 3; dx++)
                in9[dy * 3 + dx] = tile[(r + dy) * RS + (c + dx)];
#pragma unroll
        for (int j = 0; j < 3; j++) {
            float acc = bs[j];
#pragma unroll
            for (int t = 0; t < 9; t++) acc = fmaf(in9[t], w9[j][t], acc);
            __nv_bfloat16 bv = __float2bfloat16(acc);
            dst[j][p] = bv;
            float rv = __bfloat162float(bv);
            if (j == 0)      ss0 = fmaf(rv, rv, ss0);
            else if (j == 1) ss1 = fmaf(rv, rv, ss1);
            else             ss2 = fmaf(rv, rv, ss2);
        }
    }
    __shared__ float red[3][8];
    float s3[3] = {ss0, ss1, ss2};
#pragma unroll
    for (int j = 0; j < 3; j++) {
        float v = s3[j];
#pragma unroll
        for (int off = 16; off > 0; off >>= 1) v += __shfl_xor_sync(0xffffffffu, v, off);
        if ((threadIdx.x & 31) == 0) red[j][threadIdx.x >> 5] = v;
    }
    __syncthreads();
    if (threadIdx.x < 3) {
        float t = 0.f;
#pragma unroll
        for (int wd = 0; wd < 8; wd++) t += red[threadIdx.x][wd];
        int o = o0 + threadIdx.x;
        if (o < C_) g_ssq[b * C_ + o] = t;
        else        g_ssk[b * C_ + (o - C_)] = t;
    }
}

// ---------------------------------------------------------------------------
// V-conv: cin 128..191 -> fp32 v planes (no sum-of-squares needed).
// ---------------------------------------------------------------------------
__global__ __launch_bounds__(256) void conv_v_k(const float* __restrict__ x,
                                                const float* __restrict__ w,
                                                const float* __restrict__ bias) {
    const int RS = 132;
    extern __shared__ float tile[];
    int cin = blockIdx.x + 128, b = blockIdx.y;
    const float* xp = x + ((size_t)b * C_ + cin) * N_;
    for (int i = threadIdx.x; i < 130 * 130; i += 256) {
        int r = i / 130, c = i - r * 130;
        int yy = r - 1, xx = c - 1;
        float v = 0.f;
        if ((unsigned)yy < 128u && (unsigned)xx < 128u) v = xp[yy * 128 + xx];
        tile[r * RS + c] = v;
    }
    __syncthreads();

    int o0 = cin * 3;
    float w9[3][9], bs[3];
    float* dst[3];
#pragma unroll
    for (int j = 0; j < 3; j++) {
        int o = o0 + j;
        bs[j] = bias[o];
#pragma unroll
        for (int t = 0; t < 9; t++) w9[j][t] = w[o * 9 + t];
        dst[j] = g_v + ((size_t)b * C_ + (o - 2 * C_)) * N_;
    }
    for (int p = threadIdx.x; p < N_; p += 256) {
        int r = p >> 7, c = p & 127;
        float in9[9];
#pragma unroll
        for (int dy = 0; dy < 3; dy++)
#pragma unroll
            for (int dx = 0; dx < 3; dx++)
                in9[dy * 3 + dx] = tile[(r + dy) * RS + (c + dx)];
#pragma unroll
        for (int j = 0; j < 3; j++) {
            float acc = bs[j];
#pragma unroll
            for (int t = 0; t < 9; t++) acc = fmaf(in9[t], w9[j][t], acc);
            dst[j][p] = acc;
        }
    }
}

// ---------------------------------------------------------------------------
__global__ void zero_g_k() { g_G[blockIdx.x * 1024 + threadIdx.x] = 0.f; }

// ---------------------------------------------------------------------------
// K2: raw gram G[b,h] = q_h @ k_h^T over N (bf16 inputs, fp32 accumulate).
// 128 threads, 4x2 thread tile, float2 t-steps. Chunked over N with atomics.
// ---------------------------------------------------------------------------
#define GSTR 66
__global__ __launch_bounds__(128) void gram_k() {
    int chunk = blockIdx.x, h = blockIdx.y, b = blockIdx.z;
    const __nv_bfloat16* qb = g_q + ((size_t)b * C_ + h * HD_) * N_;
    const __nv_bfloat16* kb = g_k + ((size_t)b * C_ + h * HD_) * N_;
    __shared__ float qs[HD_ * GSTR], ks[HD_ * GSTR];
    int tid = threadIdx.x;
    int tx = tid & 15, ty = tid >> 4;   // tx: 16 k-pairs, ty: 8 q-quads
    float acc[4][2];
#pragma unroll
    for (int j = 0; j < 4; j++) { acc[j][0] = 0.f; acc[j][1] = 0.f; }

    int n0 = chunk * 2048;
    for (int nb = 0; nb < 2048; nb += 64) {
        // fill: 1024 bf16x2 per array, 8 iters/thread
#pragma unroll
        for (int i = 0; i < 8; i++) {
            int e = tid + i * 128;
            int cc = e >> 5, tp = (e & 31) << 1;
            const __nv_bfloat162* qp = (const __nv_bfloat162*)(qb + (size_t)cc * N_ + n0 + nb);
            const __nv_bfloat162* kp = (const __nv_bfloat162*)(kb + (size_t)cc * N_ + n0 + nb);
            float2 qf = __bfloat1622float2(qp[tp >> 1]);
            float2 kf = __bfloat1622float2(kp[tp >> 1]);
            *(float2*)&qs[cc * GSTR + tp] = qf;
            *(float2*)&ks[cc * GSTR + tp] = kf;
        }
        __syncthreads();
#pragma unroll 8
        for (int t = 0; t < 64; t += 2) {
            float2 k0 = *(const float2*)&ks[(2 * tx) * GSTR + t];
            float2 k1 = *(const float2*)&ks[(2 * tx + 1) * GSTR + t];
#pragma unroll
            for (int j = 0; j < 4; j++) {
                float2 qv = *(const float2*)&qs[(4 * ty + j) * GSTR + t];
                acc[j][0] = fmaf(qv.x, k0.x, fmaf(qv.y, k0.y, acc[j][0]));
                acc[j][1] = fmaf(qv.x, k1.x, fmaf(qv.y, k1.y, acc[j][1]));
            }
        }
        __syncthreads();
    }
    float* Gp = g_G + ((b * NH_ + h) << 10);
#pragma unroll
    for (int j = 0; j < 4; j++) {
        atomicAdd(&Gp[(4 * ty + j) * 32 + 2 * tx],     acc[j][0]);
        atomicAdd(&Gp[(4 * ty + j) * 32 + 2 * tx + 1], acc[j][1]);
    }
}

// ---------------------------------------------------------------------------
// K3a: per-(b,h) normalize+softmax, in place in g_G. One warp per (b,h).
// ---------------------------------------------------------------------------
__global__ __launch_bounds__(32) void softmax_k(const float* __restrict__ temp) {
    int h = blockIdx.x, b = blockIdx.y, cl = threadIdx.x;
    __shared__ float sinv[32];
    float nk = fmaxf(sqrtf(g_ssk[b * C_ + h * HD_ + cl]), 1e-12f);
    sinv[cl] = 1.f / nk;
    __syncwarp();
    float nq = fmaxf(sqrtf(g_ssq[b * C_ + h * HD_ + cl]), 1e-12f);
    float sc = temp[h] / nq;
    float* Gr = g_G + ((b * NH_ + h) << 10) + cl * HD_;
    float row[32], mx = -3.4e38f;
#pragma unroll
    for (int d = 0; d < 32; d++) {
        float v = Gr[d] * sc * sinv[d];
        row[d] = v;
        mx = fmaxf(mx, v);
    }
    float s = 0.f;
#pragma unroll
    for (int d = 0; d < 32; d++) { row[d] = expf(row[d] - mx); s += row[d]; }
    float inv = 1.f / s;
#pragma unroll
    for (int d = 0; d < 32; d++) Gr[d] = row[d] * inv;
}

// ---------------------------------------------------------------------------
// K3b: compose M[b] = w_out @ blockdiag(attn heads). grid (6 o-chunks, B).
// ---------------------------------------------------------------------------
__global__ __launch_bounds__(256) void compose_k(const float* __restrict__ w_out) {
    extern __shared__ float cs[];
    float* A   = cs;          // [6*32*32]
    float* Wsh = cs + 6144;   // [32*192]
    int oc = blockIdx.x, b = blockIdx.y;
    int o0 = oc * 32;
    int tid = threadIdx.x;
    const float* Gb = g_G + ((size_t)b * NH_) * 1024;
    for (int i = tid; i < 6144; i += 256) A[i] = Gb[i];
    for (int i = tid; i < 32 * 192; i += 256) {
        int o = i / 192, c = i - o * 192;
        Wsh[i] = w_out[(o0 + o) * C_ + c];
    }
    __syncthreads();
    float* Mb = g_M + (size_t)b * C_ * C_ + (size_t)o0 * C_;
    for (int i = tid; i < 32 * 192; i += 256) {
        int o = i / 192, g = i - o * 192;
        int h = g >> 5, d = g & 31;
        const float* wr = Wsh + o * 192 + h * 32;
        const float* Ar = A + h * 1024 + d;
        float acc = 0.f;
#pragma unroll
        for (int cl = 0; cl < 32; cl++) acc = fmaf(wr[cl], Ar[cl * 32], acc);
        Mb[i] = acc;
    }
}

// ---------------------------------------------------------------------------
// K4: out[b] = M[b] @ v[b] + b_out. 96-row CTAs (2/SM, 24 warps/SM),
// 384 threads, thread tile 4 rows x 8 cols, 128-col block tile,
// k double-buffered via cp.async. Packed fma.rn.f32x2 accumulation.
// ---------------------------------------------------------------------------
#define KC 32
#define MSTR 194
__global__ __launch_bounds__(384, 2) void gemm_out_k(const float* __restrict__ b_out,
                                                     float* __restrict__ out) {
    extern __shared__ float sm[];
    float* Ms = sm;                 // [96][MSTR] o-major
    float* Vs = sm + 96 * MSTR;     // [2][KC][132]
    int b = blockIdx.z;
    int o0 = blockIdx.y * 96;
    int n0 = blockIdx.x * 128;
    int tid = threadIdx.x;

    const float* Mg = g_M + (size_t)b * C_ * C_;
    const float* vb = g_v + (size_t)b * C_ * N_ + n0;

    // prefetch v chunk 0 (threads 0..255, 4 x 16B each)
    if (tid < 256) {
#pragma unroll
        for (int j = 0; j < 4; j++) {
            int e = tid + j * 256;
            int kk = e >> 5, c = (e & 31) * 4;
            CP_ASYNC16(su32(&Vs[kk * 132 + c]), vb + (size_t)kk * N_ + c);
        }
    }
    CP_COMMIT();
    // stage M rows o0..o0+95 (coalesced, conflict-free)
    for (int i = tid; i < 96 * 192; i += 384) {
        int o = i / 192, kk = i - o * 192;
        Ms[o * MSTR + kk] = Mg[(o0 + o) * C_ + kk];
    }

    int tx = tid & 15, ty = tid >> 4;   // 16 col-groups x 24 row-groups
    int r0 = ty * 4, c0 = tx * 4;

    unsigned long long acc[4][4];
#pragma unroll
    for (int j = 0; j < 4; j++)
#pragma unroll
        for (int p = 0; p < 4; p++) acc[j][p] = 0ull;

    for (int ch = 0; ch < 6; ch++) {
        if (ch < 5) {
            if (tid < 256) {
#pragma unroll
                for (int j = 0; j < 4; j++) {
                    int e = tid + j * 256;
                    int kk = e >> 5, c = (e & 31) * 4;
                    CP_ASYNC16(su32(&Vs[((ch + 1) & 1) * KC * 132 + kk * 132 + c]),
                               vb + (size_t)((ch + 1) * KC + kk) * N_ + c);
                }
            }
            CP_COMMIT();
            CP_WAIT(1);
        } else {
            CP_WAIT(0);
        }
        __syncthreads();
        const float* Vc = Vs + (ch & 1) * KC * 132;
        const float* Mc = Ms + ch * KC;
#pragma unroll 4
        for (int kk = 0; kk < KC; kk++) {
            const float* vr = Vc + kk * 132;
            ulonglong2 va  = *(const ulonglong2*)(vr + c0);
            ulonglong2 vb2 = *(const ulonglong2*)(vr + 64 + c0);
            unsigned long long vv0 = va.x, vv1 = va.y, vv2 = vb2.x, vv3 = vb2.y;
#pragma unroll
            for (int j = 0; j < 4; j++) {
                float m = Mc[(r0 + j) * MSTR + kk];
                unsigned long long mm = pack2(m, m);
                fma2(acc[j][0], mm, vv0, acc[j][0]);
                fma2(acc[j][1], mm, vv1, acc[j][1]);
                fma2(acc[j][2], mm, vv2, acc[j][2]);
                fma2(acc[j][3], mm, vv3, acc[j][3]);
            }
        }
        __syncthreads();
    }

#pragma unroll
    for (int j = 0; j < 4; j++) {
        int r = o0 + r0 + j;
        float bb = b_out[r];
        float2 f0 = unpack2(acc[j][0]), f1 = unpack2(acc[j][1]);
        float2 f2 = unpack2(acc[j][2]), f3 = unpack2(acc[j][3]);
        float4 o0v = make_float4(f0.x + bb, f0.y + bb, f1.x + bb, f1.y + bb);
        float4 o1v = make_float4(f2.x + bb, f2.y + bb, f3.x + bb, f3.y + bb);
        float* op = out + ((size_t)b * C_ + r) * N_ + n0;
        *(float4*)(op + c0)      = o0v;
        *(float4*)(op + 64 + c0) = o1v;
    }
}

// ---------------------------------------------------------------------------
extern "C" void kernel_launch(void* const* d_in, const int* in_sizes, int n_in,
                              void* d_out, int out_size) {
    const float* x     = (const float*)d_in[0];
    const float* w_qkv = (const float*)d_in[1];
    const float* b_qkv = (const float*)d_in[2];
    const float* temp  = (const float*)d_in[3];
    const float* w_out = (const float*)d_in[4];
    const float* b_out = (const float*)d_in[5];
    float* out = (float*)d_out;

    (void)in_sizes; (void)n_in; (void)out_size;

    static int inited = 0;
    const int conv_smem = 130 * 132 * 4;
    const int gemm_smem = (96 * MSTR + 2 * KC * 132) * 4;
    const int comp_smem = (6144 + 32 * 192) * 4;
    if (!inited) {
        cudaFuncSetAttribute(conv_qk_k, cudaFuncAttributeMaxDynamicSharedMemorySize, conv_smem);
        cudaFuncSetAttribute(conv_v_k,  cudaFuncAttributeMaxDynamicSharedMemorySize, conv_smem);
        cudaFuncSetAttribute(gemm_out_k, cudaFuncAttributeMaxDynamicSharedMemorySize, gemm_smem);
        cudaFuncSetAttribute(compose_k,  cudaFuncAttributeMaxDynamicSharedMemorySize, comp_smem);
        inited = 1;
    }

    // Order chosen so ncu (-s 5 -c 1 => 4th launch) profiles gram_k this round.
    conv_qk_k<<<dim3(128, B_), 256, conv_smem>>>(x, w_qkv, b_qkv);
    conv_v_k<<<dim3(64, B_), 256, conv_smem>>>(x, w_qkv, b_qkv);
    zero_g_k<<<48, 1024>>>();
    gram_k<<<dim3(8, NH_, B_), 128>>>();
    softmax_k<<<dim3(NH_, B_), 32>>>(temp);
    compose_k<<<dim3(6, B_), 256, comp_smem>>>(w_out);
    gemm_out_k<<<dim3(N_ / 128, 2, B_), 384, gemm_smem>>>(b_out, out);
}